// round 10
// baseline (speedup 1.0000x reference)
#include <cuda_runtime.h>
#include <math.h>
#include <stdint.h>

#define Bn 256
#define Mn 512
#define Dn 512
#define Cn 8
#define U1 512
#define U2 256
#define U3 128

// Scratch (device-code-only references)
__device__ float g_pooled[Bn * Dn];          // (B, D)
__device__ float g_h1[Cn * Bn * U1];         // (C, B, 512)
__device__ float g_h2[Cn * Bn * U2];         // (C, B, 256)
__device__ float g_term[Cn * Bn];            // per (c,b) loss term

// ---------------------------------------------------------------------------
// tf32 helpers
// ---------------------------------------------------------------------------
__device__ __forceinline__ uint32_t f2tf(float x) {
    uint32_t r;
    asm("cvt.rna.tf32.f32 %0, %1;" : "=r"(r) : "f"(x));
    return r;
}
__device__ __forceinline__ void mma8(float* d, const uint32_t* a, const uint32_t* b) {
    asm("mma.sync.aligned.m16n8k8.row.col.f32.tf32.tf32.f32 "
        "{%0,%1,%2,%3}, {%4,%5,%6,%7}, {%8,%9}, {%0,%1,%2,%3};"
        : "+f"(d[0]), "+f"(d[1]), "+f"(d[2]), "+f"(d[3])
        : "r"(a[0]), "r"(a[1]), "r"(a[2]), "r"(a[3]), "r"(b[0]), "r"(b[1]));
}

// ---------------------------------------------------------------------------
// 1) Masked sum pooling with LDG.128. grid (Bn), 256 threads:
//    d4 = tid&127 (float4 over D=512), mh = tid>>7 (m-half of 256 each).
//    Fixed-order combine via smem -> deterministic.
// ---------------------------------------------------------------------------
__global__ __launch_bounds__(256) void pool_kernel(const float* __restrict__ ec,
                                                   const float* __restrict__ mask) {
    const int b = blockIdx.x;
    const int tid = threadIdx.x;

    __shared__ float keep[Mn];
    __shared__ float4 part[128];

    for (int i = tid; i < Mn; i += 256)
        keep[i] = (mask[b * Mn + i] == 0.0f) ? 1.0f : 0.0f;
    __syncthreads();

    const int d4 = tid & 127;
    const int mh = tid >> 7;

    const float4* p = (const float4*)(ec + ((size_t)b * Mn + mh * 256) * Dn) + d4;
    const float* kp = keep + mh * 256;

    float4 acc = {0.f, 0.f, 0.f, 0.f};
#pragma unroll 8
    for (int m = 0; m < 256; m++) {
        float4 v = p[(size_t)m * 128];
        const float km = kp[m];
        acc.x = fmaf(v.x, km, acc.x);
        acc.y = fmaf(v.y, km, acc.y);
        acc.z = fmaf(v.z, km, acc.z);
        acc.w = fmaf(v.w, km, acc.w);
    }

    if (mh) part[d4] = acc;
    __syncthreads();
    if (!mh) {
        const float4 o = part[d4];
        float4 r = {acc.x + o.x, acc.y + o.y, acc.z + o.z, acc.w + o.w};
        ((float4*)(g_pooled + (size_t)b * Dn))[d4] = r;
    }
}

// ---------------------------------------------------------------------------
// 2) Layers 1+2: tf32x3, 64x64 tile, 8 warps 2m x 4n, warp tile 32x16.
//    Register double-buffering of BOTH A and W tiles (loads for tile t+1
//    issued before the MMA loop of tile t). PDL gate before first A read.
// ---------------------------------------------------------------------------
template <int LAYER>
__global__ __launch_bounds__(256) void gemm_tf32_kernel(
        const float* __restrict__ W, const float* __restrict__ bias) {
    constexpr int K = (LAYER == 1) ? Dn : U1;
    constexpr int N = (LAYER == 1) ? U1 : U2;
    constexpr bool AHASC = (LAYER != 1);
    const float* Aroot = (LAYER == 1) ? g_pooled : g_h1;
    float* Oroot       = (LAYER == 1) ? g_h1     : g_h2;

    const int c  = blockIdx.z;
    const int b0 = blockIdx.y * 64;
    const int n0 = blockIdx.x * 64;
    const int tid = threadIdx.x;
    const int lane = tid & 31;
    const int warp = tid >> 5;
    const int wm = warp >> 2;       // 0..1
    const int wn = warp & 3;        // 0..3
    const int g  = lane >> 2;       // 0..7
    const int tg = lane & 3;        // 0..3

    __shared__ uint32_t Ah[64][36], Al[64][36];
    __shared__ uint32_t Wh[32][68], Wl[32][68];

    float acc[2][2][4] = {};

    const float* Ag = Aroot + (AHASC ? (size_t)c * Bn * K : 0) + (size_t)b0 * K;
    const float* Wg = W + (size_t)c * K * N + n0;

    const int arow = tid >> 2;          // 0..63
    const int acol = (tid & 3) * 8;     // 0,8,16,24
    const int wrow = tid >> 3;          // 0..31
    const int wcol = (tid & 7) * 8;     // 0..56

    // W k0=0 tile is an external input — prefetch before the dependency gate
    float4 gw0 = *(const float4*)(Wg + (size_t)wrow * N + wcol);
    float4 gw1 = *(const float4*)(Wg + (size_t)wrow * N + wcol + 4);

    cudaGridDependencySynchronize();    // producer (pool / gemm1) must be done

    float4 ga0 = *(const float4*)(Ag + (size_t)arow * K + acol);
    float4 ga1 = *(const float4*)(Ag + (size_t)arow * K + acol + 4);

    for (int k0 = 0; k0 < K; k0 += 32) {
        __syncthreads();
        {
            float av[8] = {ga0.x, ga0.y, ga0.z, ga0.w, ga1.x, ga1.y, ga1.z, ga1.w};
            uint32_t h[8], l[8];
#pragma unroll
            for (int j = 0; j < 8; j++) {
                h[j] = f2tf(av[j]);
                l[j] = f2tf(av[j] - __uint_as_float(h[j]));
            }
            *(uint4*)&Ah[arow][acol]     = make_uint4(h[0], h[1], h[2], h[3]);
            *(uint4*)&Ah[arow][acol + 4] = make_uint4(h[4], h[5], h[6], h[7]);
            *(uint4*)&Al[arow][acol]     = make_uint4(l[0], l[1], l[2], l[3]);
            *(uint4*)&Al[arow][acol + 4] = make_uint4(l[4], l[5], l[6], l[7]);
        }
        {
            float wv[8] = {gw0.x, gw0.y, gw0.z, gw0.w, gw1.x, gw1.y, gw1.z, gw1.w};
            uint32_t h[8], l[8];
#pragma unroll
            for (int j = 0; j < 8; j++) {
                h[j] = f2tf(wv[j]);
                l[j] = f2tf(wv[j] - __uint_as_float(h[j]));
            }
            *(uint4*)&Wh[wrow][wcol]     = make_uint4(h[0], h[1], h[2], h[3]);
            *(uint4*)&Wh[wrow][wcol + 4] = make_uint4(h[4], h[5], h[6], h[7]);
            *(uint4*)&Wl[wrow][wcol]     = make_uint4(l[0], l[1], l[2], l[3]);
            *(uint4*)&Wl[wrow][wcol + 4] = make_uint4(l[4], l[5], l[6], l[7]);
        }
        __syncthreads();

        if (k0 + 32 < K) {  // prefetch NEXT A and W tiles; MMA hides latency
            ga0 = *(const float4*)(Ag + (size_t)arow * K + k0 + 32 + acol);
            ga1 = *(const float4*)(Ag + (size_t)arow * K + k0 + 32 + acol + 4);
            gw0 = *(const float4*)(Wg + (size_t)(k0 + 32 + wrow) * N + wcol);
            gw1 = *(const float4*)(Wg + (size_t)(k0 + 32 + wrow) * N + wcol + 4);
        }

#pragma unroll
        for (int kk = 0; kk < 4; kk++) {
            const int kb = kk * 8;
            uint32_t ah[2][4], al_[2][4], bh[2][2], bl[2][2];
#pragma unroll
            for (int mi = 0; mi < 2; mi++) {
                const int m = wm * 32 + mi * 16 + g;
                ah[mi][0]  = Ah[m][kb + tg];     ah[mi][1]  = Ah[m + 8][kb + tg];
                ah[mi][2]  = Ah[m][kb + tg + 4]; ah[mi][3]  = Ah[m + 8][kb + tg + 4];
                al_[mi][0] = Al[m][kb + tg];     al_[mi][1] = Al[m + 8][kb + tg];
                al_[mi][2] = Al[m][kb + tg + 4]; al_[mi][3] = Al[m + 8][kb + tg + 4];
            }
#pragma unroll
            for (int ni = 0; ni < 2; ni++) {
                const int n = wn * 16 + ni * 8 + g;
                bh[ni][0] = Wh[kb + tg][n]; bh[ni][1] = Wh[kb + tg + 4][n];
                bl[ni][0] = Wl[kb + tg][n]; bl[ni][1] = Wl[kb + tg + 4][n];
            }
#pragma unroll
            for (int mi = 0; mi < 2; mi++)
#pragma unroll
                for (int ni = 0; ni < 2; ni++) {
                    mma8(acc[mi][ni], ah[mi],  bh[ni]);
                    mma8(acc[mi][ni], ah[mi],  bl[ni]);
                    mma8(acc[mi][ni], al_[mi], bh[ni]);
                }
        }
    }

#pragma unroll
    for (int mi = 0; mi < 2; mi++) {
#pragma unroll
        for (int ni = 0; ni < 2; ni++) {
            const int ncol = n0 + wn * 16 + ni * 8 + tg * 2;
            const float bx = bias[c * N + ncol];
            const float by = bias[c * N + ncol + 1];
            const int r0 = b0 + wm * 32 + mi * 16 + g;
            float2 o0 = {fmaxf(acc[mi][ni][0] + bx, 0.f),
                         fmaxf(acc[mi][ni][1] + by, 0.f)};
            float2 o1 = {fmaxf(acc[mi][ni][2] + bx, 0.f),
                         fmaxf(acc[mi][ni][3] + by, 0.f)};
            *(float2*)(Oroot + ((size_t)(c * Bn + r0)) * N + ncol)     = o0;
            *(float2*)(Oroot + ((size_t)(c * Bn + r0 + 8)) * N + ncol) = o1;
        }
    }
}

// ---------------------------------------------------------------------------
// 3) Layer 3 fused with L2 normalize (round-6 proven, 16-row tile).
//    W prefetch happens BEFORE the dependency gate (overlaps gemm2 tail).
// ---------------------------------------------------------------------------
__global__ __launch_bounds__(128) void gemm3_norm_kernel(
        const float* __restrict__ W, const float* __restrict__ bias,
        float* __restrict__ zout) {
    constexpr int K = U2;   // 256
    constexpr int N = U3;   // 128
    const int b0 = blockIdx.x * 16;
    const int c  = blockIdx.y;
    const int tid = threadIdx.x;
    const int w = tid >> 5;
    const int lane = tid & 31;

    __shared__ float As[32][20];
    __shared__ float Ws[32][128];

    float acc[4][4] = {};

    const float* Ag = g_h2 + (size_t)c * Bn * K + (size_t)b0 * K;
    const float* Wg = W + (size_t)c * K * N;

    const int arow = tid >> 3;       // 0..15
    const int acol = (tid & 7) * 4;  // 0..28

    // independent W prefetch first
    float4 wreg[8];
#pragma unroll
    for (int it = 0; it < 8; it++) {
        const int f = it * 128 + tid;
        wreg[it] = *(const float4*)(Wg + (size_t)(f >> 5) * N + (f & 31) * 4);
    }

    cudaGridDependencySynchronize();    // gemm2 must be done before reading h2
    float4 areg = *(const float4*)(Ag + (size_t)arow * K + acol);

    for (int k0 = 0; k0 < K; k0 += 32) {
        __syncthreads();
        As[acol + 0][arow] = areg.x; As[acol + 1][arow] = areg.y;
        As[acol + 2][arow] = areg.z; As[acol + 3][arow] = areg.w;
#pragma unroll
        for (int it = 0; it < 8; it++) {
            const int f = it * 128 + tid;
            *(float4*)&Ws[f >> 5][(f & 31) * 4] = wreg[it];
        }
        __syncthreads();

        if (k0 + 32 < K) {
            areg = *(const float4*)(Ag + (size_t)arow * K + k0 + 32 + acol);
#pragma unroll
            for (int it = 0; it < 8; it++) {
                const int f = it * 128 + tid;
                wreg[it] = *(const float4*)(Wg + (size_t)(k0 + 32 + (f >> 5)) * N + (f & 31) * 4);
            }
        }

#pragma unroll
        for (int k = 0; k < 32; k++) {
            float4 av = *(const float4*)&As[k][w * 4];
            float4 wv = *(const float4*)&Ws[k][lane * 4];
            float a[4] = {av.x, av.y, av.z, av.w};
            float ww[4] = {wv.x, wv.y, wv.z, wv.w};
#pragma unroll
            for (int i = 0; i < 4; i++)
#pragma unroll
                for (int j = 0; j < 4; j++)
                    acc[i][j] = fmaf(a[i], ww[j], acc[i][j]);
        }
    }

    const float* bptr = bias + c * N + lane * 4;
    float bx = bptr[0], by = bptr[1], bz = bptr[2], bw = bptr[3];
#pragma unroll
    for (int i = 0; i < 4; i++) {
        float h0 = fmaxf(acc[i][0] + bx, 0.0f);
        float h1 = fmaxf(acc[i][1] + by, 0.0f);
        float h2 = fmaxf(acc[i][2] + bz, 0.0f);
        float h3 = fmaxf(acc[i][3] + bw, 0.0f);
        float ssq = h0 * h0 + h1 * h1 + h2 * h2 + h3 * h3;
#pragma unroll
        for (int o = 16; o; o >>= 1) ssq += __shfl_xor_sync(0xffffffffu, ssq, o);
        const float r = rsqrtf(fmaxf(ssq, 1e-12f));
        float4 o4 = {h0 * r, h1 * r, h2 * r, h3 * r};
        *(float4*)(zout + ((size_t)(c * Bn + b0 + w * 4 + i)) * N + lane * 4) = o4;
    }
}

// ---------------------------------------------------------------------------
// 4) Per-(c,b) contrastive term. grid (C, 16); 8 warps, 2 rows per warp.
//    Label load + reduction before the dependency gate.
// ---------------------------------------------------------------------------
#define ZPAD 132
__global__ __launch_bounds__(256) void loss_kernel(const float* __restrict__ z,
                                                   const int* __restrict__ label) {
    extern __shared__ float zs[];          // [256][ZPAD]
    __shared__ int slab[Bn];
    __shared__ int wsum[8];

    const int c = blockIdx.x;
    const int tid = threadIdx.x;
    const int lane = tid & 31;
    const int warp = tid >> 5;

    // independent: labels
    const int myl = label[tid * Cn + c];
    slab[tid] = myl;
    int s = myl;
#pragma unroll
    for (int o = 16; o; o >>= 1) s += __shfl_xor_sync(0xffffffffu, s, o);
    if (lane == 0) wsum[warp] = s;

    cudaGridDependencySynchronize();    // gemm3 must be done before reading z

    const float* zc = z + (size_t)c * Bn * U3;
    for (int idx = tid; idx < Bn * U3 / 4; idx += 256) {
        const int row = idx >> 5;
        const int c4 = idx & 31;
        float4 v = *(const float4*)(zc + (size_t)row * U3 + c4 * 4);
        *(float4*)&zs[row * ZPAD + c4 * 4] = v;
    }
    __syncthreads();
    int nump = 0;
#pragma unroll
    for (int i = 0; i < 8; i++) nump += wsum[i];

    const int bb = blockIdx.y * 16 + warp * 2;

    int lb[2];
    const float* zb[2];
#pragma unroll
    for (int i = 0; i < 2; i++) {
        lb[i] = slab[bb + i];
        zb[i] = &zs[(bb + i) * ZPAD];
    }

    float es[2] = {0.f, 0.f};
    float ps[2] = {0.f, 0.f};

#pragma unroll
    for (int kk = 0; kk < 8; kk++) {
        const int k = kk * 32 + lane;
        const float* zk = &zs[k * ZPAD];
        float s0 = 0.f, s1 = 0.f;
#pragma unroll
        for (int j = 0; j < U3; j += 4) {
            float4 x  = *(const float4*)(zk + j);
            float4 a0 = *(const float4*)(zb[0] + j);
            float4 a1 = *(const float4*)(zb[1] + j);
            s0 = fmaf(a0.x, x.x, s0); s0 = fmaf(a0.y, x.y, s0);
            s0 = fmaf(a0.z, x.z, s0); s0 = fmaf(a0.w, x.w, s0);
            s1 = fmaf(a1.x, x.x, s1); s1 = fmaf(a1.y, x.y, s1);
            s1 = fmaf(a1.z, x.z, s1); s1 = fmaf(a1.w, x.w, s1);
        }
        const int sk = slab[k];
        float sv[2] = {s0, s1};
#pragma unroll
        for (int i = 0; i < 2; i++) {
            const float ipv = (k == bb + i) ? 0.0f : sv[i] * 2.0f;  // /TEMP
            es[i] += __expf(ipv);
            if (sk == lb[i]) ps[i] += ipv;
        }
    }

#pragma unroll
    for (int i = 0; i < 2; i++) {
#pragma unroll
        for (int o = 16; o; o >>= 1) {
            es[i] += __shfl_xor_sync(0xffffffffu, es[i], o);
            ps[i] += __shfl_xor_sync(0xffffffffu, ps[i], o);
        }
    }
    if (lane == 0) {
#pragma unroll
        for (int i = 0; i < 2; i++) {
            const int numv = lb[i] ? nump : (Bn - nump);
            g_term[c * Bn + bb + i] = ps[i] / (float)numv - logf(es[i]);
        }
    }
}

// ---------------------------------------------------------------------------
// 5) Reduce terms -> losses[c]
// ---------------------------------------------------------------------------
__global__ __launch_bounds__(256) void final_kernel(float* __restrict__ out) {
    __shared__ float red[Bn];
    const int c = blockIdx.x;
    const int tid = threadIdx.x;
    cudaGridDependencySynchronize();    // loss must be done
    red[tid] = g_term[c * Bn + tid];
    __syncthreads();
    for (int s = 128; s; s >>= 1) {
        if (tid < s) red[tid] += red[tid + s];
        __syncthreads();
    }
    if (tid == 0) out[(size_t)Cn * Bn * U3 + c] = -red[0];
}

// ---------------------------------------------------------------------------
// Launch with PDL (programmatic stream serialization) on the capture stream.
// ---------------------------------------------------------------------------
template <typename F, typename... Args>
static void launch_pdl(F f, dim3 grid, dim3 block, size_t smem, Args... args) {
    cudaLaunchConfig_t cfg = {};
    cfg.gridDim = grid;
    cfg.blockDim = block;
    cfg.dynamicSmemBytes = smem;
    cfg.stream = 0;
    cudaLaunchAttribute at[1];
    at[0].id = cudaLaunchAttributeProgrammaticStreamSerialization;
    at[0].val.programmaticStreamSerializationAllowed = 1;
    cfg.attrs = at;
    cfg.numAttrs = 1;
    cudaLaunchKernelEx(&cfg, f, args...);
}

extern "C" void kernel_launch(void* const* d_in, const int* in_sizes, int n_in,
                              void* d_out, int out_size) {
    const float* ec    = (const float*)d_in[0];
    const float* mask  = (const float*)d_in[1];
    const int*   label = (const int*)d_in[2];
    const float* W1    = (const float*)d_in[3];
    const float* b1    = (const float*)d_in[4];
    const float* W2    = (const float*)d_in[5];
    const float* b2    = (const float*)d_in[6];
    const float* W3    = (const float*)d_in[7];
    const float* b3    = (const float*)d_in[8];
    float* out = (float*)d_out;

    const int loss_smem = Bn * ZPAD * (int)sizeof(float);
    static int inited = 0;
    if (!inited) {
        cudaFuncSetAttribute(loss_kernel,
                             cudaFuncAttributeMaxDynamicSharedMemorySize, loss_smem);
        inited = 1;
    }

    pool_kernel<<<Bn, 256>>>(ec, mask);
    launch_pdl(gemm_tf32_kernel<1>, dim3(U1 / 64, Bn / 64, Cn), dim3(256), 0, W1, b1);
    launch_pdl(gemm_tf32_kernel<2>, dim3(U2 / 64, Bn / 64, Cn), dim3(256), 0, W2, b2);
    launch_pdl(gemm3_norm_kernel, dim3(Bn / 16, Cn), dim3(128), 0, W3, b3, out);
    launch_pdl(loss_kernel, dim3(Cn, Bn / 16), dim3(256), (size_t)loss_smem, out, label);
    launch_pdl(final_kernel, dim3(Cn), dim3(256), 0, out);
}

// round 11
// speedup vs baseline: 1.3833x; 1.3833x over previous
#include <cuda_runtime.h>
#include <math.h>
#include <stdint.h>

#define Bn 256
#define Mn 512
#define Dn 512
#define Cn 8
#define U1 512
#define U2 256
#define U3 128

// Scratch (device-code-only references)
__device__ float g_pooled[Bn * Dn];          // (B, D)
__device__ float g_h1[Cn * Bn * U1];         // (C, B, 512)
__device__ float g_h2[Cn * Bn * U2];         // (C, B, 256)
__device__ float g_term[Cn * Bn];            // per (c,b) loss term

// ---------------------------------------------------------------------------
// bf16 helpers: pack two floats as bf16x2 (lo = first elem, hi = second),
// and hi/lo split for bf16x3 precision recovery.
// ---------------------------------------------------------------------------
__device__ __forceinline__ uint32_t packbf(float lo, float hi) {
    uint32_t r;
    asm("cvt.rn.bf16x2.f32 %0, %1, %2;" : "=r"(r) : "f"(hi), "f"(lo));
    return r;
}
__device__ __forceinline__ void split2(float x0, float x1,
                                       uint32_t& h, uint32_t& l) {
    h = packbf(x0, x1);
    const float h0 = __uint_as_float(h << 16);
    const float h1 = __uint_as_float(h & 0xffff0000u);
    l = packbf(x0 - h0, x1 - h1);
}
// D += A*B  (m16n8k16 bf16, A row-major frag, B col-major frag, fp32 accum)
__device__ __forceinline__ void mma16(float* d, const uint32_t* a, const uint32_t* b) {
    asm("mma.sync.aligned.m16n8k16.row.col.f32.bf16.bf16.f32 "
        "{%0,%1,%2,%3}, {%4,%5,%6,%7}, {%8,%9}, {%0,%1,%2,%3};"
        : "+f"(d[0]), "+f"(d[1]), "+f"(d[2]), "+f"(d[3])
        : "r"(a[0]), "r"(a[1]), "r"(a[2]), "r"(a[3]), "r"(b[0]), "r"(b[1]));
}

// ---------------------------------------------------------------------------
// 1) Masked sum pooling (round-9 proven version)
// ---------------------------------------------------------------------------
__global__ __launch_bounds__(256) void pool_kernel(const float* __restrict__ ec,
                                                   const float* __restrict__ mask) {
    const int b = blockIdx.x;
    const int dbase = blockIdx.y * 256;
    const int tid = threadIdx.x;

    __shared__ float keep[Mn];
    for (int i = tid; i < Mn; i += 256)
        keep[i] = (mask[b * Mn + i] == 0.0f) ? 1.0f : 0.0f;
    __syncthreads();

    const float* p = ec + ((size_t)b * Mn) * Dn + dbase + tid;
    float a0 = 0.f, a1 = 0.f, a2 = 0.f, a3 = 0.f;
#pragma unroll 4
    for (int m = 0; m < Mn; m += 4) {
        a0 = fmaf(p[(size_t)(m + 0) * Dn], keep[m + 0], a0);
        a1 = fmaf(p[(size_t)(m + 1) * Dn], keep[m + 1], a1);
        a2 = fmaf(p[(size_t)(m + 2) * Dn], keep[m + 2], a2);
        a3 = fmaf(p[(size_t)(m + 3) * Dn], keep[m + 3], a3);
    }
    g_pooled[b * Dn + dbase + tid] = (a0 + a1) + (a2 + a3);
}

// ---------------------------------------------------------------------------
// 2) Layers 1+2: bf16x3 tensor-core GEMM (m16n8k16). 64x64 tile, K-step 32,
//    8 warps 2m x 4n, warp tile 32x16. Smem holds bf16x2-packed k-pairs:
//    A [64][20] (16 packed k + pad), W [16][72] (64 n + pad).
//    Same prefetch/PDL structure as the proven round-9 kernel.
// ---------------------------------------------------------------------------
template <int LAYER>
__global__ __launch_bounds__(256) void gemm_bf16_kernel(
        const float* __restrict__ W, const float* __restrict__ bias) {
    constexpr int K = (LAYER == 1) ? Dn : U1;
    constexpr int N = (LAYER == 1) ? U1 : U2;
    constexpr bool AHASC = (LAYER != 1);
    const float* Aroot = (LAYER == 1) ? g_pooled : g_h1;
    float* Oroot       = (LAYER == 1) ? g_h1     : g_h2;

    const int c  = blockIdx.z;
    const int b0 = blockIdx.y * 64;
    const int n0 = blockIdx.x * 64;
    const int tid = threadIdx.x;
    const int lane = tid & 31;
    const int warp = tid >> 5;
    const int wm = warp >> 2;       // 0..1
    const int wn = warp & 3;        // 0..3
    const int g  = lane >> 2;       // 0..7
    const int tg = lane & 3;        // 0..3

    __shared__ uint32_t Ah[64][20], Al[64][20];   // [m][k2] packed bf16x2
    __shared__ uint32_t Wh[16][72], Wl[16][72];   // [k2][n] packed bf16x2

    float acc[2][2][4] = {};

    const float* Ag = Aroot + (AHASC ? (size_t)c * Bn * K : 0) + (size_t)b0 * K;
    const float* Wg = W + (size_t)c * K * N + n0;

    const int arow  = tid >> 2;          // 0..63
    const int acol2 = (tid & 3) * 4;     // packed col 0,4,8,12
    const int acolf = (tid & 3) * 8;     // float col
    const int wr2   = tid >> 4;          // 0..15 packed k row
    const int wc4   = (tid & 15) * 4;    // n col 0..60

    // W k0=0 tile is an external input — prefetch before the dependency gate
    float4 gwa = *(const float4*)(Wg + (size_t)(2 * wr2) * N + wc4);
    float4 gwb = *(const float4*)(Wg + (size_t)(2 * wr2 + 1) * N + wc4);

    cudaGridDependencySynchronize();    // producer (pool / gemm1) must be done

    for (int k0 = 0; k0 < K; k0 += 32) {
        float4 ga0 = *(const float4*)(Ag + (size_t)arow * K + k0 + acolf);
        float4 ga1 = *(const float4*)(Ag + (size_t)arow * K + k0 + acolf + 4);

        __syncthreads();
        {
            uint32_t hp[4], lp[4];
            split2(ga0.x, ga0.y, hp[0], lp[0]);
            split2(ga0.z, ga0.w, hp[1], lp[1]);
            split2(ga1.x, ga1.y, hp[2], lp[2]);
            split2(ga1.z, ga1.w, hp[3], lp[3]);
            *(uint4*)&Ah[arow][acol2] = make_uint4(hp[0], hp[1], hp[2], hp[3]);
            *(uint4*)&Al[arow][acol2] = make_uint4(lp[0], lp[1], lp[2], lp[3]);
        }
        {
            uint32_t hw[4], lw[4];
            split2(gwa.x, gwb.x, hw[0], lw[0]);   // pack along k: (k even, k odd)
            split2(gwa.y, gwb.y, hw[1], lw[1]);
            split2(gwa.z, gwb.z, hw[2], lw[2]);
            split2(gwa.w, gwb.w, hw[3], lw[3]);
            *(uint4*)&Wh[wr2][wc4] = make_uint4(hw[0], hw[1], hw[2], hw[3]);
            *(uint4*)&Wl[wr2][wc4] = make_uint4(lw[0], lw[1], lw[2], lw[3]);
        }
        __syncthreads();

        if (k0 + 32 < K) {  // prefetch next W tile (hidden by MMA loop)
            gwa = *(const float4*)(Wg + (size_t)(k0 + 32 + 2 * wr2) * N + wc4);
            gwb = *(const float4*)(Wg + (size_t)(k0 + 32 + 2 * wr2 + 1) * N + wc4);
        }

#pragma unroll
        for (int kk = 0; kk < 2; kk++) {     // two k16 steps per k32 tile
            const int kb2 = kk * 8;
            uint32_t ah[2][4], al_[2][4], bh[2][2], bl[2][2];
#pragma unroll
            for (int mi = 0; mi < 2; mi++) {
                const int m = wm * 32 + mi * 16 + g;
                ah[mi][0]  = Ah[m][kb2 + tg];     ah[mi][1]  = Ah[m + 8][kb2 + tg];
                ah[mi][2]  = Ah[m][kb2 + tg + 4]; ah[mi][3]  = Ah[m + 8][kb2 + tg + 4];
                al_[mi][0] = Al[m][kb2 + tg];     al_[mi][1] = Al[m + 8][kb2 + tg];
                al_[mi][2] = Al[m][kb2 + tg + 4]; al_[mi][3] = Al[m + 8][kb2 + tg + 4];
            }
#pragma unroll
            for (int ni = 0; ni < 2; ni++) {
                const int n = wn * 16 + ni * 8 + g;
                bh[ni][0] = Wh[kb2 + tg][n]; bh[ni][1] = Wh[kb2 + tg + 4][n];
                bl[ni][0] = Wl[kb2 + tg][n]; bl[ni][1] = Wl[kb2 + tg + 4][n];
            }
#pragma unroll
            for (int mi = 0; mi < 2; mi++)
#pragma unroll
                for (int ni = 0; ni < 2; ni++) {
                    mma16(acc[mi][ni], ah[mi],  bh[ni]);   // hi*hi
                    mma16(acc[mi][ni], ah[mi],  bl[ni]);   // hi*lo
                    mma16(acc[mi][ni], al_[mi], bh[ni]);   // lo*hi
                }
        }
    }

#pragma unroll
    for (int mi = 0; mi < 2; mi++) {
#pragma unroll
        for (int ni = 0; ni < 2; ni++) {
            const int ncol = n0 + wn * 16 + ni * 8 + tg * 2;
            const float bx = bias[c * N + ncol];
            const float by = bias[c * N + ncol + 1];
            const int r0 = b0 + wm * 32 + mi * 16 + g;
            float2 o0 = {fmaxf(acc[mi][ni][0] + bx, 0.f),
                         fmaxf(acc[mi][ni][1] + by, 0.f)};
            float2 o1 = {fmaxf(acc[mi][ni][2] + bx, 0.f),
                         fmaxf(acc[mi][ni][3] + by, 0.f)};
            *(float2*)(Oroot + ((size_t)(c * Bn + r0)) * N + ncol)     = o0;
            *(float2*)(Oroot + ((size_t)(c * Bn + r0 + 8)) * N + ncol) = o1;
        }
    }
}

// ---------------------------------------------------------------------------
// 3) Layer 3 fused with L2 normalize (round-9 proven, 16-row tile).
// ---------------------------------------------------------------------------
__global__ __launch_bounds__(128) void gemm3_norm_kernel(
        const float* __restrict__ W, const float* __restrict__ bias,
        float* __restrict__ zout) {
    constexpr int K = U2;   // 256
    constexpr int N = U3;   // 128
    const int b0 = blockIdx.x * 16;
    const int c  = blockIdx.y;
    const int tid = threadIdx.x;
    const int w = tid >> 5;
    const int lane = tid & 31;

    __shared__ float As[32][20];
    __shared__ float Ws[32][128];

    float acc[4][4] = {};

    const float* Ag = g_h2 + (size_t)c * Bn * K + (size_t)b0 * K;
    const float* Wg = W + (size_t)c * K * N;

    const int arow = tid >> 3;       // 0..15
    const int acol = (tid & 7) * 4;  // 0..28

    // independent W prefetch first
    float4 wreg[8];
#pragma unroll
    for (int it = 0; it < 8; it++) {
        const int f = it * 128 + tid;
        wreg[it] = *(const float4*)(Wg + (size_t)(f >> 5) * N + (f & 31) * 4);
    }

    cudaGridDependencySynchronize();    // gemm2 must be done before reading h2
    float4 areg = *(const float4*)(Ag + (size_t)arow * K + acol);

    for (int k0 = 0; k0 < K; k0 += 32) {
        __syncthreads();
        As[acol + 0][arow] = areg.x; As[acol + 1][arow] = areg.y;
        As[acol + 2][arow] = areg.z; As[acol + 3][arow] = areg.w;
#pragma unroll
        for (int it = 0; it < 8; it++) {
            const int f = it * 128 + tid;
            *(float4*)&Ws[f >> 5][(f & 31) * 4] = wreg[it];
        }
        __syncthreads();

        if (k0 + 32 < K) {
            areg = *(const float4*)(Ag + (size_t)arow * K + k0 + 32 + acol);
#pragma unroll
            for (int it = 0; it < 8; it++) {
                const int f = it * 128 + tid;
                wreg[it] = *(const float4*)(Wg + (size_t)(k0 + 32 + (f >> 5)) * N + (f & 31) * 4);
            }
        }

#pragma unroll
        for (int k = 0; k < 32; k++) {
            float4 av = *(const float4*)&As[k][w * 4];
            float4 wv = *(const float4*)&Ws[k][lane * 4];
            float a[4] = {av.x, av.y, av.z, av.w};
            float ww[4] = {wv.x, wv.y, wv.z, wv.w};
#pragma unroll
            for (int i = 0; i < 4; i++)
#pragma unroll
                for (int j = 0; j < 4; j++)
                    acc[i][j] = fmaf(a[i], ww[j], acc[i][j]);
        }
    }

    const float* bptr = bias + c * N + lane * 4;
    float bx = bptr[0], by = bptr[1], bz = bptr[2], bw = bptr[3];
#pragma unroll
    for (int i = 0; i < 4; i++) {
        float h0 = fmaxf(acc[i][0] + bx, 0.0f);
        float h1 = fmaxf(acc[i][1] + by, 0.0f);
        float h2 = fmaxf(acc[i][2] + bz, 0.0f);
        float h3 = fmaxf(acc[i][3] + bw, 0.0f);
        float ssq = h0 * h0 + h1 * h1 + h2 * h2 + h3 * h3;
#pragma unroll
        for (int o = 16; o; o >>= 1) ssq += __shfl_xor_sync(0xffffffffu, ssq, o);
        const float r = rsqrtf(fmaxf(ssq, 1e-12f));
        float4 o4 = {h0 * r, h1 * r, h2 * r, h3 * r};
        *(float4*)(zout + ((size_t)(c * Bn + b0 + w * 4 + i)) * N + lane * 4) = o4;
    }
}

// ---------------------------------------------------------------------------
// 4) Per-(c,b) contrastive term. grid (C, 16); 8 warps, 2 rows per warp.
// ---------------------------------------------------------------------------
#define ZPAD 132
__global__ __launch_bounds__(256) void loss_kernel(const float* __restrict__ z,
                                                   const int* __restrict__ label) {
    extern __shared__ float zs[];          // [256][ZPAD]
    __shared__ int slab[Bn];
    __shared__ int wsum[8];

    const int c = blockIdx.x;
    const int tid = threadIdx.x;
    const int lane = tid & 31;
    const int warp = tid >> 5;

    // independent: labels
    const int myl = label[tid * Cn + c];
    slab[tid] = myl;
    int s = myl;
#pragma unroll
    for (int o = 16; o; o >>= 1) s += __shfl_xor_sync(0xffffffffu, s, o);
    if (lane == 0) wsum[warp] = s;

    cudaGridDependencySynchronize();    // gemm3 must be done before reading z

    const float* zc = z + (size_t)c * Bn * U3;
    for (int idx = tid; idx < Bn * U3 / 4; idx += 256) {
        const int row = idx >> 5;
        const int c4 = idx & 31;
        float4 v = *(const float4*)(zc + (size_t)row * U3 + c4 * 4);
        *(float4*)&zs[row * ZPAD + c4 * 4] = v;
    }
    __syncthreads();
    int nump = 0;
#pragma unroll
    for (int i = 0; i < 8; i++) nump += wsum[i];

    const int bb = blockIdx.y * 16 + warp * 2;

    int lb[2];
    const float* zb[2];
#pragma unroll
    for (int i = 0; i < 2; i++) {
        lb[i] = slab[bb + i];
        zb[i] = &zs[(bb + i) * ZPAD];
    }

    float es[2] = {0.f, 0.f};
    float ps[2] = {0.f, 0.f};

#pragma unroll
    for (int kk = 0; kk < 8; kk++) {
        const int k = kk * 32 + lane;
        const float* zk = &zs[k * ZPAD];
        float s0 = 0.f, s1 = 0.f;
#pragma unroll
        for (int j = 0; j < U3; j += 4) {
            float4 x  = *(const float4*)(zk + j);
            float4 a0 = *(const float4*)(zb[0] + j);
            float4 a1 = *(const float4*)(zb[1] + j);
            s0 = fmaf(a0.x, x.x, s0); s0 = fmaf(a0.y, x.y, s0);
            s0 = fmaf(a0.z, x.z, s0); s0 = fmaf(a0.w, x.w, s0);
            s1 = fmaf(a1.x, x.x, s1); s1 = fmaf(a1.y, x.y, s1);
            s1 = fmaf(a1.z, x.z, s1); s1 = fmaf(a1.w, x.w, s1);
        }
        const int sk = slab[k];
        float sv[2] = {s0, s1};
#pragma unroll
        for (int i = 0; i < 2; i++) {
            const float ipv = (k == bb + i) ? 0.0f : sv[i] * 2.0f;  // /TEMP
            es[i] += __expf(ipv);
            if (sk == lb[i]) ps[i] += ipv;
        }
    }

#pragma unroll
    for (int i = 0; i < 2; i++) {
#pragma unroll
        for (int o = 16; o; o >>= 1) {
            es[i] += __shfl_xor_sync(0xffffffffu, es[i], o);
            ps[i] += __shfl_xor_sync(0xffffffffu, ps[i], o);
        }
    }
    if (lane == 0) {
#pragma unroll
        for (int i = 0; i < 2; i++) {
            const int numv = lb[i] ? nump : (Bn - nump);
            g_term[c * Bn + bb + i] = ps[i] / (float)numv - logf(es[i]);
        }
    }
}

// ---------------------------------------------------------------------------
// 5) Reduce terms -> losses[c]
// ---------------------------------------------------------------------------
__global__ __launch_bounds__(256) void final_kernel(float* __restrict__ out) {
    __shared__ float red[Bn];
    const int c = blockIdx.x;
    const int tid = threadIdx.x;
    cudaGridDependencySynchronize();    // loss must be done
    red[tid] = g_term[c * Bn + tid];
    __syncthreads();
    for (int s = 128; s; s >>= 1) {
        if (tid < s) red[tid] += red[tid + s];
        __syncthreads();
    }
    if (tid == 0) out[(size_t)Cn * Bn * U3 + c] = -red[0];
}

// ---------------------------------------------------------------------------
// Launch with PDL (programmatic stream serialization) on the capture stream.
// ---------------------------------------------------------------------------
template <typename F, typename... Args>
static void launch_pdl(F f, dim3 grid, dim3 block, size_t smem, Args... args) {
    cudaLaunchConfig_t cfg = {};
    cfg.gridDim = grid;
    cfg.blockDim = block;
    cfg.dynamicSmemBytes = smem;
    cfg.stream = 0;
    cudaLaunchAttribute at[1];
    at[0].id = cudaLaunchAttributeProgrammaticStreamSerialization;
    at[0].val.programmaticStreamSerializationAllowed = 1;
    cfg.attrs = at;
    cfg.numAttrs = 1;
    cudaLaunchKernelEx(&cfg, f, args...);
}

extern "C" void kernel_launch(void* const* d_in, const int* in_sizes, int n_in,
                              void* d_out, int out_size) {
    const float* ec    = (const float*)d_in[0];
    const float* mask  = (const float*)d_in[1];
    const int*   label = (const int*)d_in[2];
    const float* W1    = (const float*)d_in[3];
    const float* b1    = (const float*)d_in[4];
    const float* W2    = (const float*)d_in[5];
    const float* b2    = (const float*)d_in[6];
    const float* W3    = (const float*)d_in[7];
    const float* b3    = (const float*)d_in[8];
    float* out = (float*)d_out;

    const int loss_smem = Bn * ZPAD * (int)sizeof(float);
    static int inited = 0;
    if (!inited) {
        cudaFuncSetAttribute(loss_kernel,
                             cudaFuncAttributeMaxDynamicSharedMemorySize, loss_smem);
        inited = 1;
    }

    pool_kernel<<<dim3(Bn, 2), 256>>>(ec, mask);
    launch_pdl(gemm_bf16_kernel<1>, dim3(U1 / 64, Bn / 64, Cn), dim3(256), 0, W1, b1);
    launch_pdl(gemm_bf16_kernel<2>, dim3(U2 / 64, Bn / 64, Cn), dim3(256), 0, W2, b2);
    launch_pdl(gemm3_norm_kernel, dim3(Bn / 16, Cn), dim3(128), 0, W3, b3, out);
    launch_pdl(loss_kernel, dim3(Cn, Bn / 16), dim3(256), (size_t)loss_smem, out, label);
    launch_pdl(final_kernel, dim3(Cn), dim3(256), 0, out);
}